// round 13
// baseline (speedup 1.0000x reference)
#include <cuda_runtime.h>
#include <cstdint>

// Conv2D: x[4096,4096] fp32, w[15,15], valid -> out[4082,4082] + bias.
//
// Round 13: mma.sync TF32 banded-B conv, warp tile widened 16x32 -> 16x64.
//  - 8 n-tiles/warp share A chunks (rolling 3-chunk window) and ONE B set
//    per ky (band is shift-invariant): fragment crossbar -23% per output.
//  - tf32 convert folded into staging (LDG.128 -> cvt.rna -> STS.128).
//  - XP=100 (==4 mod 32): all fragment LDS bank-conflict-free.
//  - CTA = 4 warps stacked in oy -> 64x64 tile; grid 64x64.

typedef unsigned int u32;

#define HI 4096
#define WI 4096
#define KH 15
#define KW 15
#define OH 4082
#define OW 4082

#define NT  128
#define OYT 64
#define OXT 64
#define XR  (OYT + KH - 1)   // 78 staged rows
#define XC4 22               // float4 per staged row (88 cols >= 85 needed)
#define XP  100              // pitch (floats); 100 % 32 == 4 -> conflict-free

static __device__ __forceinline__ u32 f2tf(float f) {
    u32 r; asm("cvt.rna.tf32.f32 %0, %1;" : "=r"(r) : "f"(f)); return r;
}

__global__ __launch_bounds__(NT, 5)
void conv2d_hmma2_kernel(const float* __restrict__ x, const float* __restrict__ w,
                         const float* __restrict__ bias, float* __restrict__ out)
{
    __shared__ u32 s_X[XR * XP];       // 31200 B, tf32-converted X tile
    __shared__ u32 s_B[KH * 24 * 8];   // 11520 B, banded B per ky, [c][n]

    const int tid  = threadIdx.x;
    const int wid  = tid >> 5;
    const int lane = tid & 31;
    const int g = lane >> 2;            // 0..7
    const int e = lane & 3;             // 0..3
    const int ox0 = blockIdx.x * OXT;
    const int oy0 = blockIdx.y * OYT;

    // ---- Build banded B (tf32) for all 15 ky: B[c,n] = W[ky, c-n] ----
    for (int i = tid; i < KH * 24 * 8; i += NT) {
        const int ky = i / 192, r = i - ky * 192;
        const int c = r >> 3, n = r & 7;
        const int kx = c - n;
        s_B[i] = (kx >= 0 && kx < KW) ? f2tf(w[ky * KW + kx]) : 0u;
    }

    // ---- Stage X tile (78 x 88) with fused tf32 convert ----
    for (int i = tid; i < XR * XC4; i += NT) {
        const int r = i / XC4, q = i - r * XC4;
        const int gy = oy0 + r, gx = ox0 + 4 * q;
        uint4 t = make_uint4(0u, 0u, 0u, 0u);
        if (gy < HI && gx < WI) {       // gx mult of 4, WI%4==0 -> full float4
            const float4 v = *reinterpret_cast<const float4*>(&x[(long)gy * WI + gx]);
            t = make_uint4(f2tf(v.x), f2tf(v.y), f2tf(v.z), f2tf(v.w));
        }
        *reinterpret_cast<uint4*>(&s_X[r * XP + 4 * q]) = t;
    }
    __syncthreads();

    float d[8][4];
    #pragma unroll
    for (int j = 0; j < 8; ++j)
        #pragma unroll
        for (int k = 0; k < 4; ++k) d[j][k] = 0.f;

    const int rowb = (wid << 4) + g;    // warp oy strip + fragment row

    // ---- Main loop: 15 ky, 24 HMMA each, rolling 3-chunk A window ----
    #pragma unroll 1
    for (int ky = 0; ky < KH; ++ky) {
        const u32* r0 = &s_X[(rowb + ky) * XP];
        const u32* r1 = r0 + 8 * XP;

        const u32* Bk = &s_B[ky * 192];
        u32 B[3][2];
        #pragma unroll
        for (int s = 0; s < 3; ++s) {   // B chunk s covers c' = 8s..8s+7
            B[s][0] = Bk[(8 * s + e) * 8 + g];
            B[s][1] = Bk[(8 * s + e + 4) * 8 + g];
        }

        u32 A[3][4];                    // rotating window, slot = chunk % 3
        #pragma unroll
        for (int t = 0; t < 2; ++t) {   // preload chunks 0,1
            A[t][0] = r0[8 * t + e];     A[t][1] = r1[8 * t + e];
            A[t][2] = r0[8 * t + e + 4]; A[t][3] = r1[8 * t + e + 4];
        }

        #pragma unroll
        for (int j = 0; j < 8; ++j) {   // n-tile j uses chunks j..j+2
            const int tc = j + 2;       // load chunk j+2 into slot (j+2)%3
            const int sl = tc % 3;
            A[sl][0] = r0[8 * tc + e];     A[sl][1] = r1[8 * tc + e];
            A[sl][2] = r0[8 * tc + e + 4]; A[sl][3] = r1[8 * tc + e + 4];
            #pragma unroll
            for (int s = 0; s < 3; ++s) {
                const int as = (j + s) % 3;   // compile-time after unroll
                asm volatile(
                    "mma.sync.aligned.m16n8k8.row.col.f32.tf32.tf32.f32 "
                    "{%0,%1,%2,%3}, {%4,%5,%6,%7}, {%8,%9}, {%0,%1,%2,%3};"
                    : "+f"(d[j][0]), "+f"(d[j][1]), "+f"(d[j][2]), "+f"(d[j][3])
                    : "r"(A[as][0]), "r"(A[as][1]), "r"(A[as][2]), "r"(A[as][3]),
                      "r"(B[s][0]), "r"(B[s][1]));
            }
        }
    }

    // ---- Epilogue: bias + float2 stores (out rows only 8B-aligned) ----
    const float b = __ldg(&bias[0]);
    const int oyA = oy0 + rowb;
    const int oyB = oyA + 8;
    #pragma unroll
    for (int j = 0; j < 8; ++j) {
        const int ox = ox0 + 8 * j + 2 * e;
        if (ox + 1 < OW) {              // ox even, OW even -> no straddle
            if (oyA < OH)
                *reinterpret_cast<float2*>(&out[(long)oyA * OW + ox]) =
                    make_float2(d[j][0] + b, d[j][1] + b);
            if (oyB < OH)
                *reinterpret_cast<float2*>(&out[(long)oyB * OW + ox]) =
                    make_float2(d[j][2] + b, d[j][3] + b);
        }
    }
}

extern "C" void kernel_launch(void* const* d_in, const int* in_sizes, int n_in,
                              void* d_out, int out_size)
{
    const float* x    = (const float*)d_in[0];
    const float* w    = (const float*)d_in[1];
    const float* bias = (const float*)d_in[2];
    float* out        = (float*)d_out;

    dim3 grid((OW + OXT - 1) / OXT,   // 64
              (OH + OYT - 1) / OYT);  // 64
    conv2d_hmma2_kernel<<<grid, NT>>>(x, w, bias, out);
}

// round 14
// speedup vs baseline: 1.0429x; 1.0429x over previous
#include <cuda_runtime.h>
#include <cstdint>

// Conv2D: x[4096,4096] fp32, w[15,15], valid -> out[4082,4082] + bias.
//
// Round 14 = Round 12 (92.7us) geometry + maximum residency.
//  - Pitch 68 -> 52 floats (48 staged cols; 52 % 32 == 20 keeps fragment
//    LDS conflict-free: {20g+e} permutes 0..31). smem 27.7KB -> 8 CTAs/SM
//    (32 warps, occ 50% vs R12's 35%): the R12/R13 comparison showed this
//    latency-bound kernel scales with residency.
//  - tf32 convert fused into staging (LDG.128 -> cvt.rna -> STS.128).
//  - Fragment/band layout identical to validated R12 (rel_err 2.96e-4).

typedef unsigned int u32;

#define HI 4096
#define WI 4096
#define KH 15
#define KW 15
#define OH 4082
#define OW 4082

#define NT  128
#define OYT 64
#define OXT 32
#define XR  (OYT + KH - 1)   // 78 staged rows
#define XQ  12               // float4 per staged row (48 cols >= 46 needed)
#define XP  52               // pitch (floats); 52 % 32 == 20 -> conflict-free

static __device__ __forceinline__ u32 f2tf(float f) {
    u32 r; asm("cvt.rna.tf32.f32 %0, %1;" : "=r"(r) : "f"(f)); return r;
}

__global__ __launch_bounds__(NT, 8)
void conv2d_hmma3_kernel(const float* __restrict__ x, const float* __restrict__ w,
                         const float* __restrict__ bias, float* __restrict__ out)
{
    __shared__ u32 s_X[XR * XP];       // 16224 B, tf32-converted X tile
    __shared__ u32 s_B[KH * 24 * 8];   // 11520 B, banded B per ky, [c][n]

    const int tid  = threadIdx.x;
    const int wid  = tid >> 5;
    const int lane = tid & 31;
    const int g = lane >> 2;            // 0..7
    const int e = lane & 3;             // 0..3
    const int ox0 = blockIdx.x * OXT;
    const int oy0 = blockIdx.y * OYT;

    // ---- Build banded B (tf32) for all 15 ky: B[c,n] = W[ky, c-n] ----
    for (int i = tid; i < KH * 24 * 8; i += NT) {
        const int ky = i / 192, r = i - ky * 192;
        const int c = r >> 3, n = r & 7;
        const int kx = c - n;
        s_B[i] = (kx >= 0 && kx < KW) ? f2tf(w[ky * KW + kx]) : 0u;
    }

    // ---- Stage X tile (78 x 48) with fused tf32 convert ----
    for (int i = tid; i < XR * XQ; i += NT) {
        const int r = i / XQ, q = i - r * XQ;
        const int gy = oy0 + r, gx = ox0 + 4 * q;
        uint4 t = make_uint4(0u, 0u, 0u, 0u);
        if (gy < HI && gx < WI) {       // gx mult of 4, WI%4==0 -> full float4
            const float4 v = __ldg(reinterpret_cast<const float4*>(&x[(long)gy * WI + gx]));
            t = make_uint4(f2tf(v.x), f2tf(v.y), f2tf(v.z), f2tf(v.w));
        }
        *reinterpret_cast<uint4*>(&s_X[r * XP + 4 * q]) = t;
    }
    __syncthreads();

    float d[4][4];
    #pragma unroll
    for (int j = 0; j < 4; ++j)
        #pragma unroll
        for (int k = 0; k < 4; ++k) d[j][k] = 0.f;

    const int rowb = (wid << 4) + g;    // warp oy strip + fragment row

    // ---- Main loop: 15 ky, 12 HMMA each (layout identical to R12) ----
    #pragma unroll 1
    for (int ky = 0; ky < KH; ++ky) {
        const u32* r0 = &s_X[(rowb + ky) * XP];
        const u32* r1 = r0 + 8 * XP;
        u32 A[6][4];
        #pragma unroll
        for (int t = 0; t < 6; ++t) {   // A chunk t covers cols 8t..8t+7
            A[t][0] = r0[8 * t + e];     A[t][1] = r1[8 * t + e];
            A[t][2] = r0[8 * t + e + 4]; A[t][3] = r1[8 * t + e + 4];
        }
        const u32* Bk = &s_B[ky * 192];
        u32 B[3][2];
        #pragma unroll
        for (int s = 0; s < 3; ++s) {   // B chunk s covers c' = 8s..8s+7
            B[s][0] = Bk[(8 * s + e) * 8 + g];
            B[s][1] = Bk[(8 * s + e + 4) * 8 + g];
        }
        #pragma unroll
        for (int j = 0; j < 4; ++j)     // n-tile j uses A chunks j..j+2
            #pragma unroll
            for (int s = 0; s < 3; ++s)
                asm volatile(
                    "mma.sync.aligned.m16n8k8.row.col.f32.tf32.tf32.f32 "
                    "{%0,%1,%2,%3}, {%4,%5,%6,%7}, {%8,%9}, {%0,%1,%2,%3};"
                    : "+f"(d[j][0]), "+f"(d[j][1]), "+f"(d[j][2]), "+f"(d[j][3])
                    : "r"(A[j+s][0]), "r"(A[j+s][1]), "r"(A[j+s][2]), "r"(A[j+s][3]),
                      "r"(B[s][0]), "r"(B[s][1]));
    }

    // ---- Epilogue: bias + float2 stores (out rows only 8B-aligned) ----
    const float b = __ldg(&bias[0]);
    const int oyA = oy0 + rowb;
    const int oyB = oyA + 8;
    #pragma unroll
    for (int j = 0; j < 4; ++j) {
        const int ox = ox0 + 8 * j + 2 * e;
        if (ox + 1 < OW) {              // ox even, OW even -> no straddle
            if (oyA < OH)
                *reinterpret_cast<float2*>(&out[(long)oyA * OW + ox]) =
                    make_float2(d[j][0] + b, d[j][1] + b);
            if (oyB < OH)
                *reinterpret_cast<float2*>(&out[(long)oyB * OW + ox]) =
                    make_float2(d[j][2] + b, d[j][3] + b);
        }
    }
}

extern "C" void kernel_launch(void* const* d_in, const int* in_sizes, int n_in,
                              void* d_out, int out_size)
{
    const float* x    = (const float*)d_in[0];
    const float* w    = (const float*)d_in[1];
    const float* bias = (const float*)d_in[2];
    float* out        = (float*)d_out;

    dim3 grid((OW + OXT - 1) / OXT,   // 128
              (OH + OYT - 1) / OYT);  // 64
    conv2d_hmma3_kernel<<<grid, NT>>>(x, w, bias, out);
}

// round 15
// speedup vs baseline: 1.0627x; 1.0189x over previous
#include <cuda_runtime.h>
#include <cstdint>

// Conv2D: x[4096,4096] fp32, w[15,15], valid -> out[4082,4082] + bias.
//
// Round 15: wide warp tile (16x64, R13) at HIGH occupancy (6 CTAs/SM).
//  - CTA = 4 warps in 2x2 -> 32x128 output tile: X tile is only 46 rows x
//    148 pitch = 27.2KB (+B 11.5KB = 38.8KB -> 6 CTAs/SM, vs R13's 42.7KB
//    -> 5). Wide N cuts fragment bytes/output 1.5x vs R12/R14 geometry.
//  - Pitch 148 == 20 (mod 32): fragment LDS banks {20g+e} permute 0..31 ->
//    conflict-free. B layout banks {8e+g} permute -> conflict-free.
//  - Rolling 3-chunk A window; ONE B set per ky shared by all 8 n-tiles
//    (band shift-invariance). Fused tf32 convert in staging.

typedef unsigned int u32;

#define HI 4096
#define WI 4096
#define KH 15
#define KW 15
#define OH 4082
#define OW 4082

#define NT  128
#define CTAY 32
#define CTAX 128
#define XR  (CTAY + KH - 1)   // 46 staged rows
#define XQ  36                // float4 per row (144 cols >= 143 needed)
#define XP  148               // pitch (floats); 148 % 32 == 20 -> conflict-free

static __device__ __forceinline__ u32 f2tf(float f) {
    u32 r; asm("cvt.rna.tf32.f32 %0, %1;" : "=r"(r) : "f"(f)); return r;
}

__global__ __launch_bounds__(NT, 6)
void conv2d_hmma4_kernel(const float* __restrict__ x, const float* __restrict__ w,
                         const float* __restrict__ bias, float* __restrict__ out)
{
    __shared__ u32 s_X[XR * XP];       // 27232 B, tf32-converted X tile
    __shared__ u32 s_B[KH * 24 * 8];   // 11520 B, banded B per ky, [c][n]

    const int tid  = threadIdx.x;
    const int wid  = tid >> 5;
    const int lane = tid & 31;
    const int g  = lane >> 2;           // 0..7
    const int e  = lane & 3;            // 0..3
    const int wy = wid >> 1;            // 0..1  warp row in CTA
    const int wx = wid & 1;             // 0..1  warp col in CTA
    const int ox0 = blockIdx.x * CTAX;
    const int oy0 = blockIdx.y * CTAY;

    // ---- Build banded B (tf32) for all 15 ky: B[c,n] = W[ky, c-n] ----
    for (int i = tid; i < KH * 24 * 8; i += NT) {
        const int ky = i / 192, r = i - ky * 192;
        const int c = r >> 3, n = r & 7;
        const int kx = c - n;
        s_B[i] = (kx >= 0 && kx < KW) ? f2tf(w[ky * KW + kx]) : 0u;
    }

    // ---- Stage X tile (46 x 144) with fused tf32 convert ----
    for (int i = tid; i < XR * XQ; i += NT) {
        const int r = i / XQ, q = i - r * XQ;
        const int gy = oy0 + r, gx = ox0 + 4 * q;
        uint4 t = make_uint4(0u, 0u, 0u, 0u);
        if (gy < HI && gx < WI) {       // gx mult of 4, WI%4==0 -> full float4
            const float4 v = __ldg(reinterpret_cast<const float4*>(&x[(long)gy * WI + gx]));
            t = make_uint4(f2tf(v.x), f2tf(v.y), f2tf(v.z), f2tf(v.w));
        }
        *reinterpret_cast<uint4*>(&s_X[r * XP + 4 * q]) = t;
    }
    __syncthreads();

    float d[8][4];
    #pragma unroll
    for (int j = 0; j < 8; ++j)
        #pragma unroll
        for (int k = 0; k < 4; ++k) d[j][k] = 0.f;

    const int rowb = (wy << 4) + g;     // warp oy strip + fragment row
    const int colb = (wx << 6);         // warp col base within staged tile

    // ---- Main loop: 15 ky, 24 HMMA each, rolling 3-chunk A window ----
    #pragma unroll 1
    for (int ky = 0; ky < KH; ++ky) {
        const u32* r0 = &s_X[(rowb + ky) * XP + colb];
        const u32* r1 = r0 + 8 * XP;

        const u32* Bk = &s_B[ky * 192];
        u32 B[3][2];
        #pragma unroll
        for (int s = 0; s < 3; ++s) {   // B chunk s covers c' = 8s..8s+7
            B[s][0] = Bk[(8 * s + e) * 8 + g];
            B[s][1] = Bk[(8 * s + e + 4) * 8 + g];
        }

        u32 A[3][4];                    // rotating window, slot = chunk % 3
        #pragma unroll
        for (int t = 0; t < 2; ++t) {   // preload chunks 0,1
            A[t][0] = r0[8 * t + e];     A[t][1] = r1[8 * t + e];
            A[t][2] = r0[8 * t + e + 4]; A[t][3] = r1[8 * t + e + 4];
        }

        #pragma unroll
        for (int j = 0; j < 8; ++j) {   // n-tile j uses chunks j..j+2
            const int tc = j + 2;       // load chunk j+2 into slot (j+2)%3
            const int sl = tc % 3;
            A[sl][0] = r0[8 * tc + e];     A[sl][1] = r1[8 * tc + e];
            A[sl][2] = r0[8 * tc + e + 4]; A[sl][3] = r1[8 * tc + e + 4];
            #pragma unroll
            for (int s = 0; s < 3; ++s) {
                const int as = (j + s) % 3;   // compile-time after unroll
                asm volatile(
                    "mma.sync.aligned.m16n8k8.row.col.f32.tf32.tf32.f32 "
                    "{%0,%1,%2,%3}, {%4,%5,%6,%7}, {%8,%9}, {%0,%1,%2,%3};"
                    : "+f"(d[j][0]), "+f"(d[j][1]), "+f"(d[j][2]), "+f"(d[j][3])
                    : "r"(A[as][0]), "r"(A[as][1]), "r"(A[as][2]), "r"(A[as][3]),
                      "r"(B[s][0]), "r"(B[s][1]));
            }
        }
    }

    // ---- Epilogue: bias + float2 stores (out rows only 8B-aligned) ----
    const float b = __ldg(&bias[0]);
    const int oyA = oy0 + rowb;
    const int oyB = oyA + 8;
    #pragma unroll
    for (int j = 0; j < 8; ++j) {
        const int ox = ox0 + colb + 8 * j + 2 * e;
        if (ox + 1 < OW) {              // ox even, OW even -> no straddle
            if (oyA < OH)
                *reinterpret_cast<float2*>(&out[(long)oyA * OW + ox]) =
                    make_float2(d[j][0] + b, d[j][1] + b);
            if (oyB < OH)
                *reinterpret_cast<float2*>(&out[(long)oyB * OW + ox]) =
                    make_float2(d[j][2] + b, d[j][3] + b);
        }
    }
}

extern "C" void kernel_launch(void* const* d_in, const int* in_sizes, int n_in,
                              void* d_out, int out_size)
{
    const float* x    = (const float*)d_in[0];
    const float* w    = (const float*)d_in[1];
    const float* bias = (const float*)d_in[2];
    float* out        = (float*)d_out;

    dim3 grid((OW + CTAX - 1) / CTAX,   // 32
              (OH + CTAY - 1) / CTAY);  // 128
    conv2d_hmma4_kernel<<<grid, NT>>>(x, w, bias, out);
}